// round 12
// baseline (speedup 1.0000x reference)
#include <cuda_runtime.h>

// Problem shape (fixed by the dataset): feature1/feature2 are (8, 256, 512, 512) fp32, NCHW.
#define NB 8
#define NC 256
#define HWD 512
#define POOLK 16
#define PH (HWD / POOLK)   // 32 pooled rows
#define PW (HWD / POOLK)   // 32 pooled cols
#define NSAMP (NB * PH * PW)    // 8192 samples per channel
#define NSTRIPS (NB * NC * PH)  // 65536 strips total
#define STRIPS_PER_BLK 2
#define NBLOCKS (NSTRIPS / STRIPS_PER_BLK)  // 32768

// Per-channel accumulators: [c*5 + {0:sx, 1:sy, 2:sxx, 3:syy, 4:sxy}]
// Statically zero-initialized; the fused finalize (last block) restores them
// to zero after reading, so every launch / graph replay sees zeros.
__device__ double g_acc[NC * 5];
__device__ unsigned int g_count;  // arrival counter, reset by last block

// Each block handles 2 strips sharing the same (c, ph): strip ids
// bid and bid + NBLOCKS (b differs by 4). Per strip: 16 rows x 512 cols of
// each feature, 8 warps x 2 rows, fully coalesced float4 streaming loads.
// Double-buffered smem lets warp 0's per-strip reduce overlap the other
// warps' loads for the next strip. One atomic flush of the 5 local double
// stats per block; the LAST block performs the finalize inline.
__global__ __launch_bounds__(256) void pool_stats_kernel(
    const float* __restrict__ f1, const float* __restrict__ f2, float* out)
{
    const int bid = blockIdx.x;
    const int ph  = bid & (PH - 1);          // 5 bits
    const int ch  = (bid >> 5) & (NC - 1);   // 8 bits
    const int b0  = bid >> 13;               // 0..3

    const int t = threadIdx.x;
    const int w = t >> 5;   // warp 0..7
    const int l = t & 31;   // lane

    __shared__ float sm1[STRIPS_PER_BLK][8][32];
    __shared__ float sm2[STRIPS_PER_BLK][8][32];

    // local stat accumulators (meaningful on warp 0, lane 0)
    double acc0 = 0.0, acc1 = 0.0, acc2 = 0.0, acc3 = 0.0, acc4 = 0.0;

#pragma unroll
    for (int j = 0; j < STRIPS_PER_BLK; j++) {
        const int b = b0 + 4 * j;

        // First of the two rows this warp owns in this strip
        const long long row0 =
            ((long long)(b * NC + ch) * HWD + (long long)ph * POOLK + 2 * w);
        const float4* p1 = (const float4*)(f1 + row0 * HWD) + l;
        const float4* p2 = (const float4*)(f2 + row0 * HWD) + l;

        float part1[4] = {0.f, 0.f, 0.f, 0.f};
        float part2[4] = {0.f, 0.f, 0.f, 0.f};
#pragma unroll
        for (int r = 0; r < 2; r++) {
            float4 v[4], u[4];
#pragma unroll
            for (int i = 0; i < 4; i++) v[i] = __ldcs(&p1[r * (HWD / 4) + i * 32]);
#pragma unroll
            for (int i = 0; i < 4; i++) u[i] = __ldcs(&p2[r * (HWD / 4) + i * 32]);
#pragma unroll
            for (int i = 0; i < 4; i++) {
                part1[i] += (v[i].x + v[i].y) + (v[i].z + v[i].w);
                part2[i] += (u[i].x + u[i].y) + (u[i].z + u[i].w);
            }
        }

        // Reduce each part[i] over the 4-lane group {4g..4g+3} -> pooled col i*8+g
#pragma unroll
        for (int i = 0; i < 4; i++) {
            part1[i] += __shfl_xor_sync(0xffffffffu, part1[i], 1);
            part1[i] += __shfl_xor_sync(0xffffffffu, part1[i], 2);
            part2[i] += __shfl_xor_sync(0xffffffffu, part2[i], 1);
            part2[i] += __shfl_xor_sync(0xffffffffu, part2[i], 2);
        }

        if ((l & 3) == 0) {
            const int g = l >> 2;
#pragma unroll
            for (int i = 0; i < 4; i++) {
                sm1[j][w][i * 8 + g] = part1[i];
                sm2[j][w][i * 8 + g] = part2[i];
            }
        }
        __syncthreads();  // buffer j published; warps 1-7 move straight to next strip's loads

        if (w == 0) {
            float xs = 0.f, ys = 0.f;
#pragma unroll
            for (int i = 0; i < 8; i++) { xs += sm1[j][i][l]; ys += sm2[j][i][l]; }
            // pooled values for (b, ch, ph, pw=l)
            const float x = xs * (1.0f / (POOLK * POOLK));
            const float y = ys * (1.0f / (POOLK * POOLK));

            float a1 = x, a2 = y, a11 = x * x, a22 = y * y, a12 = x * y;
#pragma unroll
            for (int off = 16; off > 0; off >>= 1) {
                a1  += __shfl_down_sync(0xffffffffu, a1,  off);
                a2  += __shfl_down_sync(0xffffffffu, a2,  off);
                a11 += __shfl_down_sync(0xffffffffu, a11, off);
                a22 += __shfl_down_sync(0xffffffffu, a22, off);
                a12 += __shfl_down_sync(0xffffffffu, a12, off);
            }
            if (l == 0) {
                acc0 += (double)a1;
                acc1 += (double)a2;
                acc2 += (double)a11;
                acc3 += (double)a22;
                acc4 += (double)a12;
            }
        }
    }

    // One flush of the block's stats
    if (t == 0) {
        atomicAdd(&g_acc[ch * 5 + 0], acc0);
        atomicAdd(&g_acc[ch * 5 + 1], acc1);
        atomicAdd(&g_acc[ch * 5 + 2], acc2);
        atomicAdd(&g_acc[ch * 5 + 3], acc3);
        atomicAdd(&g_acc[ch * 5 + 4], acc4);
    }

    // ---- last-block detection ----
    __shared__ bool is_last;
    if (t == 0) {
        __threadfence();  // make this block's g_acc atomics visible before counting
        unsigned int old = atomicAdd(&g_count, 1u);
        is_last = (old == (unsigned int)(NBLOCKS - 1));
    }
    __syncthreads();
    if (!is_last) return;

    // ---- fused finalize: thread t owns channel t ----
    const int c = t;
    const double n = (double)NSAMP;

    const double s1  = __ldcg(&g_acc[c * 5 + 0]);
    const double s2  = __ldcg(&g_acc[c * 5 + 1]);
    const double s11 = __ldcg(&g_acc[c * 5 + 2]);
    const double s22 = __ldcg(&g_acc[c * 5 + 3]);
    const double s12 = __ldcg(&g_acc[c * 5 + 4]);

    // Reset state for the next launch / graph replay.
    g_acc[c * 5 + 0] = 0.0;
    g_acc[c * 5 + 1] = 0.0;
    g_acc[c * 5 + 2] = 0.0;
    g_acc[c * 5 + 3] = 0.0;
    g_acc[c * 5 + 4] = 0.0;
    if (t == 0) g_count = 0u;

    const double m1 = s1 / n;
    const double m2 = s2 / n;
    // biased covariance (torch.mean of products of deviations)
    const double cov = s12 / n - m1 * m2;
    // unbiased std (torch.std, ddof = 1)
    const double v1 = (s11 - s1 * s1 / n) / (n - 1.0);
    const double v2 = (s22 - s2 * s2 / n) / (n - 1.0);
    const double corr = cov / (sqrt(v1) * sqrt(v2) + 1e-8);

    // block reduction of |corr| over 256 channels
    double ac = fabs(corr);
#pragma unroll
    for (int off = 16; off > 0; off >>= 1)
        ac += __shfl_down_sync(0xffffffffu, ac, off);

    __shared__ double smd[8];
    if (l == 0) smd[w] = ac;
    __syncthreads();
    if (t == 0) {
        double tot = 0.0;
#pragma unroll
        for (int i = 0; i < 8; i++) tot += smd[i];
        out[0] = (float)(1.0 - tot / (double)NC);
    }
}

extern "C" void kernel_launch(void* const* d_in, const int* in_sizes, int n_in,
                              void* d_out, int out_size) {
    const float* f1 = (const float*)d_in[0];
    const float* f2 = (const float*)d_in[1];
    float* out = (float*)d_out;

    pool_stats_kernel<<<NBLOCKS, 256>>>(f1, f2, out);
}